// round 1
// baseline (speedup 1.0000x reference)
#include <cuda_runtime.h>
#include <math.h>

#define T    32
#define Bz   32
#define NIN  512
#define NH   1024
#define NOUT 256
#define NBLK 148
#define NTH  256

// ---------------- persistent state (device globals; no allocation) ----------
__device__ float dS[T * Bz * NH];       // relu(relu(x)@W_i)      [m=(t,b)][k]
__device__ float dZ[T * Bz * NH];       // relu(S@W_z)            [m][k]
__device__ float dZCt[T * NH * Bz];     // Z@W_c transposed       [t][j][b]
__device__ float dHist[T * NH * Bz];    // intermediate h per step [t][j][b]
__device__ float dHcur[NH * Bz];        // carry hs               [j][b]
__device__ float dOt[NH * Bz];          // o = relu(h@W_ho)       [j][b]
__device__ float dPart[4 * NH * Bz];    // split-K partials
__device__ float dDots[T * Bz];         // scaled dot coefficients [tau][b]
__device__ unsigned gArrive;            // zero-initialized
__device__ volatile unsigned gEpoch;    // monotonically increasing across replays

// ---------------- software grid barrier -------------------------------------
__device__ __forceinline__ void gsync() {
    __syncthreads();
    if (threadIdx.x == 0) {
        __threadfence();
        unsigned e = gEpoch;
        if (atomicAdd(&gArrive, 1u) == NBLK - 1u) {
            gArrive = 0u;
            __threadfence();
            atomicAdd((unsigned*)&gEpoch, 1u);
        } else {
            while (gEpoch == e) { __nanosleep(32); }
        }
        __threadfence();
    }
    __syncthreads();
}

// ---------------- big GEMM: C[M,N] = op(A[M,K] @ W[K,N]) --------------------
// BM=64, BN=64, BK=16, 256 threads, 4x4 per-thread microtile.
template <bool RIN, bool ROUT, bool TST>
__device__ void gemm_big(const float* __restrict__ A, const float* __restrict__ W,
                         float* __restrict__ C, int M, int N, int K) {
    __shared__ float As[16][64];   // [k][m]
    __shared__ float Bs[16][64];   // [k][n]
    int tid = threadIdx.x;
    int tx = tid & 15, ty = tid >> 4;
    int tilesN = N >> 6;
    int njobs = (M >> 6) * tilesN;
    for (int job = blockIdx.x; job < njobs; job += NBLK) {
        int m0 = (job / tilesN) << 6;
        int n0 = (job % tilesN) << 6;
        float acc[4][4];
#pragma unroll
        for (int i = 0; i < 4; i++)
#pragma unroll
            for (int j = 0; j < 4; j++) acc[i][j] = 0.f;

        for (int k0 = 0; k0 < K; k0 += 16) {
            {   // A tile -> As[k][m]
                int r = tid >> 2;
                int c4 = (tid & 3) << 2;
                float4 v = *reinterpret_cast<const float4*>(A + (size_t)(m0 + r) * K + k0 + c4);
                if (RIN) {
                    v.x = fmaxf(v.x, 0.f); v.y = fmaxf(v.y, 0.f);
                    v.z = fmaxf(v.z, 0.f); v.w = fmaxf(v.w, 0.f);
                }
                As[c4 + 0][r] = v.x; As[c4 + 1][r] = v.y;
                As[c4 + 2][r] = v.z; As[c4 + 3][r] = v.w;
            }
            {   // W tile -> Bs[k][n]
                int r = tid >> 4;
                int c4 = (tid & 15) << 2;
                *reinterpret_cast<float4*>(&Bs[r][c4]) =
                    *reinterpret_cast<const float4*>(W + (size_t)(k0 + r) * N + n0 + c4);
            }
            __syncthreads();
#pragma unroll
            for (int k = 0; k < 16; k++) {
                float a0 = As[k][ty * 4 + 0];
                float a1 = As[k][ty * 4 + 1];
                float a2 = As[k][ty * 4 + 2];
                float a3 = As[k][ty * 4 + 3];
                float4 b4 = *reinterpret_cast<float4*>(&Bs[k][tx * 4]);
                acc[0][0] += a0 * b4.x; acc[0][1] += a0 * b4.y; acc[0][2] += a0 * b4.z; acc[0][3] += a0 * b4.w;
                acc[1][0] += a1 * b4.x; acc[1][1] += a1 * b4.y; acc[1][2] += a1 * b4.z; acc[1][3] += a1 * b4.w;
                acc[2][0] += a2 * b4.x; acc[2][1] += a2 * b4.y; acc[2][2] += a2 * b4.z; acc[2][3] += a2 * b4.w;
                acc[3][0] += a3 * b4.x; acc[3][1] += a3 * b4.y; acc[3][2] += a3 * b4.z; acc[3][3] += a3 * b4.w;
            }
            __syncthreads();
        }
#pragma unroll
        for (int i = 0; i < 4; i++) {
#pragma unroll
            for (int j = 0; j < 4; j++) {
                float v = acc[i][j];
                if (ROUT) v = fmaxf(v, 0.f);
                int m = m0 + ty * 4 + i;
                int n = n0 + tx * 4 + j;
                if (TST) {
                    // m = t*32 + b  ->  C[t][n][b]
                    C[(((size_t)(m >> 5) * NH) + n) * Bz + (m & 31)] = v;
                } else {
                    C[(size_t)m * N + n] = v;
                }
            }
        }
    }
}

// ---------------- skinny recurrent GEMM (M=32), split-K partials ------------
// A layout [k][b] (k-major, 32 b fast). Writes partials part[ks][j*32+b].
// One job = (jt, ks): BN=32 columns, K-slice of 256. 256 threads, 2x2 microtile.
__device__ void gemm_rec_job(const float* __restrict__ At, const float* __restrict__ W,
                             float* __restrict__ part, int N, int jt, int ks) {
    __shared__ float As[32][32];   // [k][b]
    __shared__ float Ws[32][32];   // [k][j]
    int tid = threadIdx.x;
    int jg = tid & 15;     // j pair
    int bg = tid >> 4;     // b pair
    int j0 = jt << 5;
    int k0 = ks << 8;
    float c00 = 0.f, c01 = 0.f, c10 = 0.f, c11 = 0.f;
    for (int kk = 0; kk < 256; kk += 32) {
        *reinterpret_cast<float4*>(&As[0][0] + 4 * tid) =
            *reinterpret_cast<const float4*>(At + (size_t)(k0 + kk) * Bz + 4 * tid);
        int r = tid >> 3;
        int c = (tid & 7) << 2;
        *reinterpret_cast<float4*>(&Ws[r][c]) =
            *reinterpret_cast<const float4*>(W + (size_t)(k0 + kk + r) * N + j0 + c);
        __syncthreads();
#pragma unroll
        for (int k = 0; k < 32; k++) {
            float a0 = As[k][bg * 2 + 0];
            float a1 = As[k][bg * 2 + 1];
            float w0 = Ws[k][jg * 2 + 0];
            float w1 = Ws[k][jg * 2 + 1];
            c00 += a0 * w0; c01 += a0 * w1;
            c10 += a1 * w0; c11 += a1 * w1;
        }
        __syncthreads();
    }
    float* p = part + (size_t)ks * N * Bz;
    int jj = j0 + jg * 2;
    int b0 = bg * 2;
    p[(size_t)(jj + 0) * Bz + b0 + 0] = c00;
    p[(size_t)(jj + 1) * Bz + b0 + 0] = c01;
    p[(size_t)(jj + 0) * Bz + b0 + 1] = c10;
    p[(size_t)(jj + 1) * Bz + b0 + 1] = c11;
}

// ---------------- main persistent kernel ------------------------------------
__global__ void __launch_bounds__(NTH, 1)
memnet_kernel(const float* __restrict__ x,   const float* __restrict__ Wi,
              const float* __restrict__ Wz,  const float* __restrict__ Wc,
              const float* __restrict__ Wh,  const float* __restrict__ Who,
              const float* __restrict__ Wo,  const float* __restrict__ lam_p,
              const float* __restrict__ eta_p, const float* __restrict__ g_p,
              const float* __restrict__ b_p, float* __restrict__ out) {
    int tid  = threadIdx.x;
    int lane = tid & 31;
    int w    = tid >> 5;

    // ---- precompute (state-independent): S, Z, ZC^T; init h0 = 0 ----
    for (int i = blockIdx.x * NTH + tid; i < NH * Bz; i += NBLK * NTH) dHcur[i] = 0.f;
    gemm_big<true,  true,  false>(x,  Wi, dS,   T * Bz, NH, NIN);
    gsync();
    gemm_big<false, true,  false>(dS, Wz, dZ,   T * Bz, NH, NH);
    gsync();
    gemm_big<false, false, true >(dZ, Wc, dZCt, T * Bz, NH, NH);
    gsync();

    const float lam = lam_p[0];
    const float eta = eta_p[0];

    // ---- recurrence ----
    for (int t = 0; t < T; t++) {
        const float* zc = dZCt + (size_t)t * NH * Bz;
        float* Ht = dHist + (size_t)t * NH * Bz;

        // Phase A: partials of h_prev @ W_h
        for (int job = blockIdx.x; job < 128; job += NBLK)
            gemm_rec_job(dHcur, Wh, dPart, NH, job & 31, job >> 5);
        gsync();

        // Phase A-reduce: h_new = relu(zc + sum partials) -> Hist[t]
        for (int i = blockIdx.x * NTH + tid; i < NH * Bz; i += NBLK * NTH) {
            float v = dPart[i] + dPart[NH * Bz + i] + dPart[2 * NH * Bz + i]
                    + dPart[3 * NH * Bz + i] + zc[i];
            Ht[i] = fmaxf(v, 0.f);
        }
        gsync();

        // Phase B: partials of h_new @ W_h; plus scaled history dot-products
        {
            int njob = 128 + t + 1;
            for (int job = blockIdx.x; job < njob; job += NBLK) {
                if (job < 128) {
                    gemm_rec_job(Ht, Wh, dPart, NH, job & 31, job >> 5);
                } else {
                    int tau = job - 128;
                    const float* Hs = dHist + (size_t)tau * NH * Bz;
                    float a = 0.f;
                    int kbeg = w << 7;
#pragma unroll 8
                    for (int k = kbeg; k < kbeg + 128; k++)
                        a += Ht[(size_t)k * Bz + lane] * Hs[(size_t)k * Bz + lane];
                    __shared__ float red[8][32];
                    __syncthreads();
                    red[w][lane] = a;
                    __syncthreads();
                    if (w == 0) {
                        float s = 0.f;
#pragma unroll
                        for (int i = 0; i < 8; i++) s += red[i][lane];
                        s *= eta * powf(lam, (float)(t - tau));
                        dDots[tau * Bz + lane] = s;
                    }
                    __syncthreads();
                }
            }
        }
        gsync();

        // Phase C: hs = hW + zc + sum_tau d[tau]*H[tau]; batchnorm over b; -> hcur
        {
            int gw = blockIdx.x * 8 + w;   // one warp per hidden unit j
            if (gw < NH) {
                int idx = gw * Bz + lane;
                float acc = dPart[idx] + dPart[NH * Bz + idx] + dPart[2 * NH * Bz + idx]
                          + dPart[3 * NH * Bz + idx] + zc[idx];
                for (int tau = 0; tau <= t; tau++)
                    acc += dDots[tau * Bz + lane] * dHist[(size_t)tau * NH * Bz + idx];
                float mu = acc;
#pragma unroll
                for (int o = 16; o > 0; o >>= 1) mu += __shfl_xor_sync(0xffffffffu, mu, o);
                mu *= (1.f / 32.f);
                float dv = acc - mu;
                float vv = dv * dv;
#pragma unroll
                for (int o = 16; o > 0; o >>= 1) vv += __shfl_xor_sync(0xffffffffu, vv, o);
                float sig = sqrtf(vv * (1.f / 32.f));
                dHcur[idx] = fmaxf(g_p[gw] * dv / sig + b_p[gw], 0.f);
            }
        }
        gsync();
    }

    // ---- head: o = relu(h @ W_ho) ----
    for (int job = blockIdx.x; job < 128; job += NBLK)
        gemm_rec_job(dHcur, Who, dPart, NH, job & 31, job >> 5);
    gsync();
    for (int i = blockIdx.x * NTH + tid; i < NH * Bz; i += NBLK * NTH) {
        float v = dPart[i] + dPart[NH * Bz + i] + dPart[2 * NH * Bz + i] + dPart[3 * NH * Bz + i];
        dOt[i] = fmaxf(v, 0.f);
    }
    gsync();

    // ---- y = relu(o @ W_o) ----  N=256 -> 8 j-tiles * 4 k-slices = 32 jobs
    for (int job = blockIdx.x; job < 32; job += NBLK)
        gemm_rec_job(dOt, Wo, dPart, NOUT, job & 7, job >> 3);
    gsync();
    for (int i = blockIdx.x * NTH + tid; i < NOUT * Bz; i += NBLK * NTH) {
        float v = dPart[i] + dPart[NOUT * Bz + i] + dPart[2 * NOUT * Bz + i] + dPart[3 * NOUT * Bz + i];
        int n = i >> 5, b = i & 31;
        out[(size_t)b * NOUT + n] = fmaxf(v, 0.f);
    }
}

extern "C" void kernel_launch(void* const* d_in, const int* in_sizes, int n_in,
                              void* d_out, int out_size) {
    (void)in_sizes; (void)n_in; (void)out_size;
    memnet_kernel<<<NBLK, NTH>>>(
        (const float*)d_in[0],  // x_in
        (const float*)d_in[1],  // W_i
        (const float*)d_in[2],  // W_z
        (const float*)d_in[3],  // W_c
        (const float*)d_in[4],  // W_h
        (const float*)d_in[5],  // W_ho
        (const float*)d_in[6],  // W_o
        (const float*)d_in[7],  // lam
        (const float*)d_in[8],  // eta
        (const float*)d_in[9],  // g
        (const float*)d_in[10], // b
        (float*)d_out);
}

// round 2
// speedup vs baseline: 1.1439x; 1.1439x over previous
#include <cuda_runtime.h>
#include <math.h>

#define T    32
#define Bz   32
#define NIN  512
#define NH   1024
#define NOUT 256
#define NBLK 296      // 2 CTAs/SM * 148 SMs, guaranteed resident via launch_bounds
#define NTH  256

// ---------------- persistent state (device globals; no allocation) ----------
__device__ float dS[T * Bz * NH];       // relu(relu(x)@W_i)      [m=(t,b)][k]
__device__ float dZ[T * Bz * NH];       // relu(S@W_z)            [m][k]
__device__ float dZCt[T * NH * Bz];     // Z@W_c transposed       [t][j][b]
__device__ float dHist[T * NH * Bz];    // intermediate h per step [t][j][b]
__device__ float dHcur[NH * Bz];        // carry hs               [j][b]
__device__ float dOt[NH * Bz];          // o = relu(h@W_ho)       [j][b]
__device__ float dPart[8 * NH * Bz];    // split-K partials (8 slices)
__device__ float dDots[T * Bz];         // scaled dot coefficients [tau][b]
__device__ unsigned gArrive;            // zero-initialized
__device__ volatile unsigned gEpoch;    // monotonically increasing across replays

// ---------------- packed f32x2 helpers (FFMA2 only reachable via PTX) -------
static __device__ __forceinline__ unsigned long long pk2(float v) {
    unsigned long long r;
    asm("mov.b64 %0, {%1, %1};" : "=l"(r) : "f"(v));
    return r;
}
static __device__ __forceinline__ void ffma2(unsigned long long& d,
                                             unsigned long long a,
                                             unsigned long long b) {
    asm("fma.rn.f32x2 %0, %1, %2, %0;" : "+l"(d) : "l"(a), "l"(b));
}
static __device__ __forceinline__ float2 up2(unsigned long long v) {
    float2 f;
    asm("mov.b64 {%0, %1}, %2;" : "=f"(f.x), "=f"(f.y) : "l"(v));
    return f;
}

// ---------------- software grid barrier (persistent kernel only) ------------
__device__ __forceinline__ void gsync() {
    __syncthreads();
    if (threadIdx.x == 0) {
        __threadfence();
        unsigned e = gEpoch;
        if (atomicAdd(&gArrive, 1u) == NBLK - 1u) {
            gArrive = 0u;
            __threadfence();
            atomicAdd((unsigned*)&gEpoch, 1u);
        } else {
            while (gEpoch == e) { __nanosleep(16); }
        }
        __threadfence();
    }
    __syncthreads();
}

// ---------------- big GEMM device body: C[M,N] = op(A[M,K] @ W[K,N]) --------
// One CTA = one 64x64 tile (blockIdx.x). BK=16, 256 threads, 4x4 microtile,
// packed f32x2 accumulation.
template <bool RIN, bool ROUT, bool TST>
__device__ __forceinline__ void gemm_big_dev(const float* __restrict__ A,
                                             const float* __restrict__ W,
                                             float* __restrict__ C,
                                             int M, int N, int K) {
    __shared__ __align__(16) float As[16][64];   // [k][m]
    __shared__ __align__(16) float Bs[16][64];   // [k][n]
    int tid = threadIdx.x;
    int tx = tid & 15, ty = tid >> 4;
    int tilesN = N >> 6;
    int m0 = (blockIdx.x / tilesN) << 6;
    int n0 = (blockIdx.x % tilesN) << 6;

    unsigned long long acc[4][2];
#pragma unroll
    for (int i = 0; i < 4; i++) { acc[i][0] = 0ull; acc[i][1] = 0ull; }

    for (int k0 = 0; k0 < K; k0 += 16) {
        {   // A tile -> As[k][m]
            int r = tid >> 2;
            int c4 = (tid & 3) << 2;
            float4 v = *reinterpret_cast<const float4*>(A + (size_t)(m0 + r) * K + k0 + c4);
            if (RIN) {
                v.x = fmaxf(v.x, 0.f); v.y = fmaxf(v.y, 0.f);
                v.z = fmaxf(v.z, 0.f); v.w = fmaxf(v.w, 0.f);
            }
            As[c4 + 0][r] = v.x; As[c4 + 1][r] = v.y;
            As[c4 + 2][r] = v.z; As[c4 + 3][r] = v.w;
        }
        {   // W tile -> Bs[k][n]
            int r = tid >> 4;
            int c4 = (tid & 15) << 2;
            *reinterpret_cast<float4*>(&Bs[r][c4]) =
                *reinterpret_cast<const float4*>(W + (size_t)(k0 + r) * N + n0 + c4);
        }
        __syncthreads();
#pragma unroll
        for (int k = 0; k < 16; k++) {
            float4 a4 = *reinterpret_cast<float4*>(&As[k][ty * 4]);
            ulonglong2 b2 = *reinterpret_cast<ulonglong2*>(&Bs[k][tx * 4]);
            unsigned long long a0 = pk2(a4.x), a1 = pk2(a4.y);
            unsigned long long a2 = pk2(a4.z), a3 = pk2(a4.w);
            ffma2(acc[0][0], a0, b2.x); ffma2(acc[0][1], a0, b2.y);
            ffma2(acc[1][0], a1, b2.x); ffma2(acc[1][1], a1, b2.y);
            ffma2(acc[2][0], a2, b2.x); ffma2(acc[2][1], a2, b2.y);
            ffma2(acc[3][0], a3, b2.x); ffma2(acc[3][1], a3, b2.y);
        }
        __syncthreads();
    }
#pragma unroll
    for (int i = 0; i < 4; i++) {
        float2 u0 = up2(acc[i][0]);
        float2 u1 = up2(acc[i][1]);
        float vals[4] = {u0.x, u0.y, u1.x, u1.y};
#pragma unroll
        for (int j = 0; j < 4; j++) {
            float v = vals[j];
            if (ROUT) v = fmaxf(v, 0.f);
            int m = m0 + ty * 4 + i;
            int n = n0 + tx * 4 + j;
            if (TST) {
                // m = t*32 + b  ->  C[t][n][b]
                C[(((size_t)(m >> 5) * NH) + n) * Bz + (m & 31)] = v;
            } else {
                C[(size_t)m * N + n] = v;
            }
        }
    }
}

// Precompute kernels (standalone launches -> high occupancy)
__global__ void __launch_bounds__(256) k_gemm_s(const float* __restrict__ x,
                                                const float* __restrict__ Wi) {
    gemm_big_dev<true, true, false>(x, Wi, dS, T * Bz, NH, NIN);
}
__global__ void __launch_bounds__(256) k_gemm_z(const float* __restrict__ Wz) {
    gemm_big_dev<false, true, false>(dS, Wz, dZ, T * Bz, NH, NH);
}
__global__ void __launch_bounds__(256) k_gemm_zc(const float* __restrict__ Wc) {
    gemm_big_dev<false, false, true>(dZ, Wc, dZCt, T * Bz, NH, NH);
}

// ---------------- skinny recurrent GEMM (M=32), split-K 8 x 128 -------------
// A layout [k][b]. Tile = 32b x 32j, K-slice 128. 256 threads, 2x2 microtile,
// packed f32x2, vector LDS.
__device__ void rec_job(const float* __restrict__ At, const float* __restrict__ W,
                        float* __restrict__ part, int N, int jt, int ks) {
    __shared__ __align__(16) float As[32][32];   // [k][b]
    __shared__ __align__(16) float Ws[32][32];   // [k][j]
    int tid = threadIdx.x;
    int jg = tid & 15;     // j pair
    int bg = tid >> 4;     // b pair
    int j0 = jt << 5;
    int k0 = ks << 7;      // K-slice of 128
    unsigned long long c0 = 0ull, c1 = 0ull;
    for (int kk = 0; kk < 128; kk += 32) {
        *reinterpret_cast<float4*>(&As[0][0] + 4 * tid) =
            *reinterpret_cast<const float4*>(At + (size_t)(k0 + kk) * Bz + 4 * tid);
        int r = tid >> 3;
        int c = (tid & 7) << 2;
        *reinterpret_cast<float4*>(&Ws[r][c]) =
            *reinterpret_cast<const float4*>(W + (size_t)(k0 + kk + r) * N + j0 + c);
        __syncthreads();
#pragma unroll
        for (int k = 0; k < 32; k++) {
            float2 a2 = *reinterpret_cast<float2*>(&As[k][bg * 2]);
            unsigned long long wp = *reinterpret_cast<unsigned long long*>(&Ws[k][jg * 2]);
            ffma2(c0, pk2(a2.x), wp);
            ffma2(c1, pk2(a2.y), wp);
        }
        __syncthreads();
    }
    float* p = part + (size_t)ks * N * Bz;
    float2 u0 = up2(c0), u1 = up2(c1);
    int jj = j0 + jg * 2;
    int b0 = bg * 2;
    p[(size_t)(jj + 0) * Bz + b0 + 0] = u0.x;
    p[(size_t)(jj + 1) * Bz + b0 + 0] = u0.y;
    p[(size_t)(jj + 0) * Bz + b0 + 1] = u1.x;
    p[(size_t)(jj + 1) * Bz + b0 + 1] = u1.y;
}

// ---------------- persistent recurrence kernel ------------------------------
__global__ void __launch_bounds__(NTH, 2)
memnet_rec_kernel(const float* __restrict__ Wh,  const float* __restrict__ Who,
                  const float* __restrict__ Wo,  const float* __restrict__ lam_p,
                  const float* __restrict__ eta_p, const float* __restrict__ g_p,
                  const float* __restrict__ b_p, float* __restrict__ out) {
    int tid  = threadIdx.x;
    int lane = tid & 31;
    int w    = tid >> 5;

    const float lam = lam_p[0];
    const float eta = eta_p[0];

    for (int t = 0; t < T; t++) {
        const float* zc = dZCt + (size_t)t * NH * Bz;
        float* Ht = dHist + (size_t)t * NH * Bz;

        // Phase A: partials of h_prev @ W_h  (h_prev = 0 at t=0 -> skip)
        if (t > 0) {
            for (int job = blockIdx.x; job < 256; job += NBLK)
                rec_job(dHcur, Wh, dPart, NH, job & 31, job >> 5);
            gsync();
        }

        // Phase A-reduce: h_new = relu(zc + sum partials) -> Hist[t]
        for (int i = blockIdx.x * NTH + tid; i < NH * Bz; i += NBLK * NTH) {
            float v = zc[i];
            if (t > 0) {
#pragma unroll
                for (int s = 0; s < 8; s++) v += dPart[(size_t)s * NH * Bz + i];
            }
            Ht[i] = fmaxf(v, 0.f);
        }
        gsync();

        // Phase B: partials of h_new @ W_h; plus scaled history dot-products
        {
            int njob = 256 + t + 1;
            for (int job = blockIdx.x; job < njob; job += NBLK) {
                if (job < 256) {
                    rec_job(Ht, Wh, dPart, NH, job & 31, job >> 5);
                } else {
                    int tau = job - 256;
                    const float* Hs = dHist + (size_t)tau * NH * Bz;
                    float a = 0.f;
                    int kbeg = w << 7;
#pragma unroll 8
                    for (int k = kbeg; k < kbeg + 128; k++)
                        a += Ht[(size_t)k * Bz + lane] * Hs[(size_t)k * Bz + lane];
                    __shared__ float red[8][32];
                    __syncthreads();
                    red[w][lane] = a;
                    __syncthreads();
                    if (w == 0) {
                        float s = 0.f;
#pragma unroll
                        for (int i = 0; i < 8; i++) s += red[i][lane];
                        s *= eta * powf(lam, (float)(t - tau));
                        dDots[tau * Bz + lane] = s;
                    }
                    __syncthreads();
                }
            }
        }
        gsync();

        // Phase C: hs = hW + zc + sum_tau d[tau]*H[tau]; batchnorm over b
        {
            int gw = blockIdx.x * 8 + w;   // one warp per hidden unit j
            if (gw < NH) {
                int idx = gw * Bz + lane;
                float acc = zc[idx];
#pragma unroll
                for (int s = 0; s < 8; s++) acc += dPart[(size_t)s * NH * Bz + idx];
                for (int tau = 0; tau <= t; tau++)
                    acc += dDots[tau * Bz + lane] * dHist[(size_t)tau * NH * Bz + idx];
                float mu = acc;
#pragma unroll
                for (int o = 16; o > 0; o >>= 1) mu += __shfl_xor_sync(0xffffffffu, mu, o);
                mu *= (1.f / 32.f);
                float dv = acc - mu;
                float vv = dv * dv;
#pragma unroll
                for (int o = 16; o > 0; o >>= 1) vv += __shfl_xor_sync(0xffffffffu, vv, o);
                float sig = sqrtf(vv * (1.f / 32.f));
                dHcur[idx] = fmaxf(g_p[gw] * dv / sig + b_p[gw], 0.f);
            }
        }
        gsync();
    }

    // ---- head: o = relu(h @ W_ho) ----
    for (int job = blockIdx.x; job < 256; job += NBLK)
        rec_job(dHcur, Who, dPart, NH, job & 31, job >> 5);
    gsync();
    for (int i = blockIdx.x * NTH + tid; i < NH * Bz; i += NBLK * NTH) {
        float v = 0.f;
#pragma unroll
        for (int s = 0; s < 8; s++) v += dPart[(size_t)s * NH * Bz + i];
        dOt[i] = fmaxf(v, 0.f);
    }
    gsync();

    // ---- y = relu(o @ W_o) ----  N=256: 8 j-tiles * 8 k-slices = 64 jobs
    for (int job = blockIdx.x; job < 64; job += NBLK)
        rec_job(dOt, Wo, dPart, NOUT, job & 7, job >> 3);
    gsync();
    for (int i = blockIdx.x * NTH + tid; i < NOUT * Bz; i += NBLK * NTH) {
        float v = 0.f;
#pragma unroll
        for (int s = 0; s < 8; s++) v += dPart[(size_t)s * NOUT * Bz + i];
        int n = i >> 5, b = i & 31;
        out[(size_t)b * NOUT + n] = fmaxf(v, 0.f);
    }
}

extern "C" void kernel_launch(void* const* d_in, const int* in_sizes, int n_in,
                              void* d_out, int out_size) {
    (void)in_sizes; (void)n_in; (void)out_size;
    const float* x   = (const float*)d_in[0];
    const float* Wi  = (const float*)d_in[1];
    const float* Wz  = (const float*)d_in[2];
    const float* Wc  = (const float*)d_in[3];
    const float* Wh  = (const float*)d_in[4];
    const float* Who = (const float*)d_in[5];
    const float* Wo  = (const float*)d_in[6];
    const float* lam = (const float*)d_in[7];
    const float* eta = (const float*)d_in[8];
    const float* g   = (const float*)d_in[9];
    const float* b   = (const float*)d_in[10];

    // precompute chain: 16x16 = 256 tiles of 64x64 each
    k_gemm_s<<<256, 256>>>(x, Wi);
    k_gemm_z<<<256, 256>>>(Wz);
    k_gemm_zc<<<256, 256>>>(Wc);
    // persistent recurrence + head
    memnet_rec_kernel<<<NBLK, NTH>>>(Wh, Who, Wo, lam, eta, g, b, (float*)d_out);
}